// round 14
// baseline (speedup 1.0000x reference)
#include <cuda_runtime.h>
#include <cuda_fp16.h>
#include <cstdint>
#include <math.h>

#define E_   30
#define NB_  12
#define F_   1024
#define H_   32
#define B_   8192
#define L_   128
#define EPS_ 1e-12f

#define EPC   2
#define NEG   15
#define ROWS  256
#define FROWS 64           // fma rows (warps 0-1, flat loop from L2)
#define KC    32
#define NCH   (F_ / KC)

__device__ float g_w[E_ * B_ * NB_];
__device__ float g_XT[F_ * B_];            // X transposed (F,B) for fma warps
__device__ __half g_Xh[B_ * F_], g_Xl[B_ * F_];

// ---- per-buffer smem offsets (bytes); tensor side only ----
#define OXHI  0            // 192 rows x 80B = 15360
#define OXLO  15360        // 15360
#define OWH   30720        // 2e x 32 x 80B = 5120
#define BUFSZ 35840
#define SMEM_BYTES (2 * BUFSZ)             // 71680 -> 2 CTAs/SM
// epilogue aliases
#define EP_HS  0                           // 2e x 256 x 33 f32 = 67584
#define EP_W2  67584                       // 3072
#define EP_B2  70656
#define EP_BW  70784

__device__ __forceinline__ uint32_t smem_u32(const void* p) {
    uint32_t a;
    asm("{ .reg .u64 t; cvta.to.shared.u64 t, %1; cvt.u32.u64 %0, t; }"
        : "=r"(a) : "l"(p));
    return a;
}
#define CP16(dst, src) \
    asm volatile("cp.async.cg.shared.global [%0], [%1], 16;" \
        :: "r"((uint32_t)(dst)), "l"(src) : "memory")
#define CPCOMMIT() asm volatile("cp.async.commit_group;" ::: "memory")
#define CPWAIT0()  asm volatile("cp.async.wait_group 0;" ::: "memory")
#define TBAR()     asm volatile("bar.sync 1, 192;" ::: "memory")

__device__ __forceinline__ void ldmx4(uint32_t* r, uint32_t a) {
    asm volatile("ldmatrix.sync.aligned.m8n8.x4.shared.b16 {%0,%1,%2,%3}, [%4];"
        : "=r"(r[0]), "=r"(r[1]), "=r"(r[2]), "=r"(r[3]) : "r"(a));
}
__device__ __forceinline__ void ldmx4t(uint32_t* r, uint32_t a) {
    asm volatile("ldmatrix.sync.aligned.m8n8.x4.trans.shared.b16 {%0,%1,%2,%3}, [%4];"
        : "=r"(r[0]), "=r"(r[1]), "=r"(r[2]), "=r"(r[3]) : "r"(a));
}
__device__ __forceinline__ void mma_f16(float* c, const uint32_t* a, const uint32_t* b) {
    asm volatile(
        "mma.sync.aligned.m16n8k16.row.col.f32.f16.f16.f32 "
        "{%0,%1,%2,%3}, {%4,%5,%6,%7}, {%8,%9}, {%0,%1,%2,%3};"
        : "+f"(c[0]), "+f"(c[1]), "+f"(c[2]), "+f"(c[3])
        : "r"(a[0]), "r"(a[1]), "r"(a[2]), "r"(a[3]), "r"(b[0]), "r"(b[1]));
}
__device__ __forceinline__ uint32_t packh2(__half a, __half b) {
    return (uint32_t)__half_as_ushort(a) | ((uint32_t)__half_as_ushort(b) << 16);
}
__device__ __forceinline__ float selu(float v) {
    const float S  = 1.0507009873554805f;
    const float SA = 1.0507009873554805f * 1.6732632423543772f;
    return (v > 0.f) ? S * v : SA * (__expf(v) - 1.f);
}

// ---------------------------------------------------------------------------
// Prep: g_XT = X^T (f32) + fp16 hi/lo split of X. grid (F/32, B/32), 256 thr.
// ---------------------------------------------------------------------------
__global__ __launch_bounds__(256) void prep_kernel(const float* __restrict__ X) {
    __shared__ float t[32][33];
    const int fx = blockIdx.x * 32, by = blockIdx.y * 32;
    const int lx = threadIdx.x & 31, ly = threadIdx.x >> 5;
    #pragma unroll
    for (int i = 0; i < 32; i += 8) {
        size_t gi = (size_t)(by + ly + i) * F_ + fx + lx;
        float v = X[gi];
        t[ly + i][lx] = v;
        __half h = __float2half(v);
        g_Xh[gi] = h;
        g_Xl[gi] = __float2half(v - __half2float(h));
    }
    __syncthreads();
    #pragma unroll
    for (int i = 0; i < 32; i += 8)
        g_XT[(size_t)(fx + ly + i) * B_ + by + lx] = t[lx][ly + i];
}

// ---------------------------------------------------------------------------
// Kernel A: decoupled hybrid. Warps 0-1: fp32 FFMA flat-loop (rows 0-63).
//           Warps 2-7: fp16x2 mma.sync, double-buffered (rows 64-255).
// grid (32, 15), 256 threads, 2 CTAs/SM.
// ---------------------------------------------------------------------------
__global__ void __launch_bounds__(256, 2) mlp_hybrid_kernel(
    const float* __restrict__ X,
    const float* __restrict__ bw,
    const float* __restrict__ W1,
    const float* __restrict__ b1,
    const float* __restrict__ W2,
    const float* __restrict__ b2)
{
    extern __shared__ char smem[];
    const uint32_t sb = smem_u32(smem);
    const int tid  = threadIdx.x;
    const int w    = tid >> 5;
    const int lane = tid & 31;
    const int b0   = blockIdx.x * ROWS;
    const int e0   = blockIdx.y * EPC;

    float* Hsf = (float*)(smem + EP_HS);

    if (w < 2) {
        // ============ FMA ROLE: rows 0..63, fp32, straight from L2 ============
        const int rg = tid & 7;          // row group: rows rg*8 .. rg*8+7
        const int cg = tid >> 3;         // col group: cols cg*4 .. cg*4+3
        const float* __restrict__ xtp = g_XT + b0 + rg * 8;

        float acc[EPC][8][4];
        #pragma unroll
        for (int e = 0; e < EPC; e++)
            #pragma unroll
            for (int r = 0; r < 8; r++)
                #pragma unroll
                for (int c = 0; c < 4; c++) acc[e][r][c] = 0.f;

        #pragma unroll 4
        for (int k = 0; k < F_; k++) {
            float4 a0 = __ldg(reinterpret_cast<const float4*>(xtp + (size_t)k * B_));
            float4 a1 = __ldg(reinterpret_cast<const float4*>(xtp + (size_t)k * B_ + 4));
            float av[8] = {a0.x, a0.y, a0.z, a0.w, a1.x, a1.y, a1.z, a1.w};
            #pragma unroll
            for (int e = 0; e < EPC; e++) {
                float4 wv = __ldg(reinterpret_cast<const float4*>(
                    &W1[((size_t)(e0 + e) * F_ + k) * H_ + cg * 4]));
                float wc[4] = {wv.x, wv.y, wv.z, wv.w};
                #pragma unroll
                for (int r = 0; r < 8; r++)
                    #pragma unroll
                    for (int c = 0; c < 4; c++)
                        acc[e][r][c] = fmaf(av[r], wc[c], acc[e][r][c]);
            }
        }
        __syncthreads();   // wait: tensor mainloop done (smem buffers free)
        #pragma unroll
        for (int e = 0; e < EPC; e++)
            #pragma unroll
            for (int r = 0; r < 8; r++)
                #pragma unroll
                for (int c = 0; c < 4; c++) {
                    int row = rg * 8 + r, col = cg * 4 + c;
                    float v = acc[e][r][c] + __ldg(&b1[(e0 + e) * H_ + col]);
                    Hsf[e * 8448 + row * 33 + col] = selu(v);
                }
    } else {
        // ============ TENSOR ROLE: rows 64..255, fp16x2 mma.sync ============
        const int tid_t = tid - 64;       // 0..191
        const int tw    = w - 2;          // 0..5

        auto stageX = [&](int c, int p) {
            const int k0 = c * KC;
            const uint32_t bb = sb + p * BUFSZ;
            #pragma unroll
            for (int it = 0; it < 8; it++) {
                int t = it * 192 + tid_t;
                if (t < 768) {
                    int row = t >> 2, q = t & 3;
                    CP16(bb + OXHI + row * 80 + q * 16,
                         g_Xh + (size_t)(b0 + FROWS + row) * F_ + k0 + q * 8);
                } else {
                    int t2 = t - 768;
                    int row = t2 >> 2, q = t2 & 3;
                    CP16(bb + OXLO + row * 80 + q * 16,
                         g_Xl + (size_t)(b0 + FROWS + row) * F_ + k0 + q * 8);
                }
            }
        };
        auto ldgW = [&](float4* wv, int c) {
            const int k0 = c * KC;
            #pragma unroll
            for (int it = 0; it < 3; it++) {
                int g = it * 192 + tid_t;
                if (g < 512) {
                    int e = g >> 8, r = g & 255, kr = r >> 3, q = r & 7;
                    wv[it] = *reinterpret_cast<const float4*>(
                        &W1[((size_t)(e0 + e) * F_ + k0 + kr) * H_ + q * 4]);
                }
            }
        };
        auto stsW = [&](const float4* wv, int p) {
            #pragma unroll
            for (int it = 0; it < 3; it++) {
                int g = it * 192 + tid_t;
                if (g < 512) {
                    int e = g >> 8, r = g & 255, kr = r >> 3, q = r & 7;
                    uint32_t h01 = packh2(__float2half(wv[it].x), __float2half(wv[it].y));
                    uint32_t h23 = packh2(__float2half(wv[it].z), __float2half(wv[it].w));
                    *reinterpret_cast<uint2*>(smem + p * BUFSZ + OWH
                        + e * 2560 + kr * 80 + q * 8) = make_uint2(h01, h23);
                }
            }
        };

        {
            float4 w0[3];
            ldgW(w0, 0);
            stageX(0, 0); CPCOMMIT();
            stsW(w0, 0);
            CPWAIT0(); TBAR();
        }

        float acct[EPC][2][4][4];
        #pragma unroll
        for (int e = 0; e < EPC; e++)
            #pragma unroll
            for (int mt = 0; mt < 2; mt++)
                #pragma unroll
                for (int nt = 0; nt < 4; nt++)
                    #pragma unroll
                    for (int j = 0; j < 4; j++) acct[e][mt][nt][j] = 0.f;

        const int lr16 = lane & 15, lq16 = (lane >> 4) * 16;
        float4 wv[3];
        for (int c = 0; c < NCH; c++) {
            const int p = c & 1;
            if (c + 1 < NCH) {
                ldgW(wv, c + 1);
                stageX(c + 1, p ^ 1); CPCOMMIT();
            }
            const uint32_t bb = sb + p * BUFSZ;
            #pragma unroll
            for (int ks = 0; ks < 2; ks++) {
                uint32_t Ah[2][4], Al[2][4];
                #pragma unroll
                for (int mt = 0; mt < 2; mt++) {
                    uint32_t ar = bb + OXHI +
                        (uint32_t)((tw * 32 + mt * 16 + lr16) * 80 + ks * 32 + lq16);
                    ldmx4(Ah[mt], ar);
                    ldmx4(Al[mt], ar + (OXLO - OXHI));
                }
                #pragma unroll
                for (int e = 0; e < EPC; e++) {
                    #pragma unroll
                    for (int np = 0; np < 2; np++) {
                        uint32_t Bh[4];
                        ldmx4t(Bh, bb + OWH +
                            (uint32_t)(e * 2560 + (ks * 16 + lr16) * 80 + np * 32 + lq16));
                        #pragma unroll
                        for (int mt = 0; mt < 2; mt++) {
                            #pragma unroll
                            for (int t = 0; t < 2; t++) {
                                float* C = acct[e][mt][np * 2 + t];
                                mma_f16(C, Ah[mt], &Bh[t * 2]);
                                mma_f16(C, Al[mt], &Bh[t * 2]);
                            }
                        }
                    }
                }
            }
            if (c + 1 < NCH) stsW(wv, p ^ 1);
            CPWAIT0(); TBAR();
        }
        __syncthreads();   // join fma role; smem switches to epilogue layout
        #pragma unroll
        for (int e = 0; e < EPC; e++)
            #pragma unroll
            for (int mt = 0; mt < 2; mt++) {
                int r0 = FROWS + tw * 32 + mt * 16 + (lane >> 2);
                #pragma unroll
                for (int nt = 0; nt < 4; nt++) {
                    int col = nt * 8 + (lane & 3) * 2;
                    float ba  = __ldg(&b1[(e0 + e) * H_ + col]);
                    float bb2 = __ldg(&b1[(e0 + e) * H_ + col + 1]);
                    const float* C = acct[e][mt][nt];
                    Hsf[e * 8448 + r0 * 33 + col]           = selu(C[0] + ba);
                    Hsf[e * 8448 + r0 * 33 + col + 1]       = selu(C[1] + bb2);
                    Hsf[e * 8448 + (r0 + 8) * 33 + col]     = selu(C[2] + ba);
                    Hsf[e * 8448 + (r0 + 8) * 33 + col + 1] = selu(C[3] + bb2);
                }
            }
    }

    // stage layer-2 constants
    float* W2s = (float*)(smem + EP_W2);
    float* b2s = (float*)(smem + EP_B2);
    float* bws = (float*)(smem + EP_BW);
    for (int t = tid; t < EPC * H_ * NB_; t += 256)
        W2s[t] = W2[(size_t)e0 * H_ * NB_ + t];
    if (tid < EPC * NB_) {
        b2s[tid] = b2[e0 * NB_ + tid];
        bws[tid] = bw[e0 * NB_ + tid];
    }
    __syncthreads();

    // layer 2 + weight update + signed-L1 normalize (row = tid)
    #pragma unroll
    for (int e = 0; e < EPC; e++) {
        float h[H_];
        #pragma unroll
        for (int hh = 0; hh < H_; hh++) h[hh] = Hsf[e * 8448 + tid * 33 + hh];

        float ew[NB_]; float s = 0.f;
        #pragma unroll
        for (int n = 0; n < NB_; n++) { ew[n] = __expf(bws[e * NB_ + n]); s += ew[n]; }
        const float inv_s = 1.f / fmaxf(s, EPS_);

        float upd[NB_]; float sa = 0.f;
        #pragma unroll
        for (int n = 0; n < NB_; n++) {
            float a2 = b2s[e * NB_ + n];
            #pragma unroll
            for (int hh = 0; hh < H_; hh++)
                a2 = fmaf(h[hh], W2s[e * H_ * NB_ + hh * NB_ + n], a2);
            float u = fmaf(ew[n], inv_s, a2);
            upd[n] = u;
            sa += fabsf(u);
        }
        const float inv = 1.f / fmaxf(sa, EPS_);

        float4* dst = reinterpret_cast<float4*>(
            &g_w[((size_t)(e0 + e) * B_ + b0 + tid) * NB_]);
        dst[0] = make_float4(upd[0] * inv, upd[1] * inv, upd[2]  * inv, upd[3]  * inv);
        dst[1] = make_float4(upd[4] * inv, upd[5] * inv, upd[6]  * inv, upd[7]  * inv);
        dst[2] = make_float4(upd[8] * inv, upd[9] * inv, upd[10] * inv, upd[11] * inv);
    }
}

// ---------------------------------------------------------------------------
// Kernel B: mixed = w @ D, softmax over L (|mixed| < 1 -> no max pass).
// ---------------------------------------------------------------------------
__global__ __launch_bounds__(128, 7) void mix_softmax_kernel(
    const float* __restrict__ D, float* __restrict__ out)
{
    const int warp = threadIdx.x >> 5;
    const int lane = threadIdx.x & 31;
    const size_t b = (size_t)blockIdx.x * 4 + warp;

    float4 Dreg[NB_];
    #pragma unroll
    for (int n = 0; n < NB_; n++)
        Dreg[n] = *reinterpret_cast<const float4*>(
            &D[(b * NB_ + n) * L_ + lane * 4]);

    const float* wp = &g_w[b * NB_];
    float wv_next = (lane < NB_) ? wp[lane] : 0.f;

    for (int e = 0; e < E_; e++) {
        float wvv = wv_next;
        if (e + 1 < E_)
            wv_next = (lane < NB_) ? wp[(size_t)(e + 1) * B_ * NB_ + lane] : 0.f;

        float4 v = make_float4(0.f, 0.f, 0.f, 0.f);
        #pragma unroll
        for (int n = 0; n < NB_; n++) {
            float wn = __shfl_sync(0xffffffffu, wvv, n);
            v.x = fmaf(wn, Dreg[n].x, v.x);
            v.y = fmaf(wn, Dreg[n].y, v.y);
            v.z = fmaf(wn, Dreg[n].z, v.z);
            v.w = fmaf(wn, Dreg[n].w, v.w);
        }
        float e0 = __expf(v.x), e1 = __expf(v.y);
        float e2 = __expf(v.z), e3 = __expf(v.w);
        float sm = (e0 + e1) + (e2 + e3);
        #pragma unroll
        for (int off = 16; off > 0; off >>= 1)
            sm += __shfl_xor_sync(0xffffffffu, sm, off);
        const float inv = 1.f / sm;
        *reinterpret_cast<float4*>(&out[((size_t)e * B_ + b) * L_ + lane * 4]) =
            make_float4(e0 * inv, e1 * inv, e2 * inv, e3 * inv);
    }
}

// ---------------------------------------------------------------------------
extern "C" void kernel_launch(void* const* d_in, const int* in_sizes, int n_in,
                              void* d_out, int out_size)
{
    const float* D  = (const float*)d_in[0];
    const float* X  = (const float*)d_in[1];
    const float* bw = (const float*)d_in[2];
    const float* W1 = (const float*)d_in[3];
    const float* b1 = (const float*)d_in[4];
    const float* W2 = (const float*)d_in[5];
    const float* b2 = (const float*)d_in[6];
    float* out = (float*)d_out;

    cudaFuncSetAttribute(mlp_hybrid_kernel,
                         cudaFuncAttributeMaxDynamicSharedMemorySize, SMEM_BYTES);

    dim3 gP(F_ / 32, B_ / 32);
    prep_kernel<<<gP, 256>>>(X);
    dim3 gA(B_ / ROWS, NEG);
    mlp_hybrid_kernel<<<gA, 256, SMEM_BYTES>>>(X, bw, W1, b1, W2, b2);
    mix_softmax_kernel<<<B_ / 4, 128>>>(D, out);
}

// round 15
// speedup vs baseline: 1.0627x; 1.0627x over previous
#include <cuda_runtime.h>
#include <cuda_fp16.h>
#include <cstdint>
#include <math.h>

#define E_   30
#define NB_  12
#define F_   1024
#define H_   32
#define B_   8192
#define L_   128
#define EPS_ 1e-12f

#define EPC  3            // emotions per CTA
#define NEG  10           // emotion groups
#define ROWS 128          // B rows per CTA
#define KC   32           // k per chunk
#define NCH  (F_ / KC)    // 32 chunks

__device__ float g_w[E_ * B_ * NB_];

// ---------------- smem layout (bytes) ----------------
#define OFF_BW   0                       // 3*12 f
#define OFF_B2   256
#define OFF_B1   512                     // 3*32 f
#define OFF_W2   1024                    // 3*384 f = 4608B
#define OFF_X    5888
#define BUFSZ    28160                   // XHI 10240 + XLO 10240 + WH 7680
#define XHI(p)   (OFF_X + (p) * BUFSZ)
#define XLO(p)   (XHI(p) + 10240)
#define WH(p)    (XHI(p) + 20480)
#define SMEM_BYTES (OFF_X + 2 * BUFSZ)   // 62208 -> 2 CTAs/SM

__device__ __forceinline__ uint32_t smem_u32(const void* p) {
    uint32_t a;
    asm("{ .reg .u64 t; cvta.to.shared.u64 t, %1; cvt.u32.u64 %0, t; }"
        : "=r"(a) : "l"(p));
    return a;
}
__device__ __forceinline__ void ldmx4(uint32_t* r, uint32_t a) {
    asm volatile("ldmatrix.sync.aligned.m8n8.x4.shared.b16 {%0,%1,%2,%3}, [%4];"
        : "=r"(r[0]), "=r"(r[1]), "=r"(r[2]), "=r"(r[3]) : "r"(a));
}
__device__ __forceinline__ void ldmx4t(uint32_t* r, uint32_t a) {
    asm volatile("ldmatrix.sync.aligned.m8n8.x4.trans.shared.b16 {%0,%1,%2,%3}, [%4];"
        : "=r"(r[0]), "=r"(r[1]), "=r"(r[2]), "=r"(r[3]) : "r"(a));
}
__device__ __forceinline__ void mma_f16(float* c, const uint32_t* a, const uint32_t* b) {
    asm volatile(
        "mma.sync.aligned.m16n8k16.row.col.f32.f16.f16.f32 "
        "{%0,%1,%2,%3}, {%4,%5,%6,%7}, {%8,%9}, {%0,%1,%2,%3};"
        : "+f"(c[0]), "+f"(c[1]), "+f"(c[2]), "+f"(c[3])
        : "r"(a[0]), "r"(a[1]), "r"(a[2]), "r"(a[3]), "r"(b[0]), "r"(b[1]));
}
// split fp32 pair into hi/lo fp16 packed b32
__device__ __forceinline__ void split2h(float x, float y, uint32_t& hi, uint32_t& lo) {
    __half hx = __float2half(x);
    __half hy = __float2half(y);
    __half lx = __float2half(x - __half2float(hx));
    __half ly = __float2half(y - __half2float(hy));
    hi = (uint32_t)__half_as_ushort(hx) | ((uint32_t)__half_as_ushort(hy) << 16);
    lo = (uint32_t)__half_as_ushort(lx) | ((uint32_t)__half_as_ushort(ly) << 16);
}
__device__ __forceinline__ uint32_t cvt2h(float x, float y) {
    __half hx = __float2half(x);
    __half hy = __float2half(y);
    return (uint32_t)__half_as_ushort(hx) | ((uint32_t)__half_as_ushort(hy) << 16);
}
__device__ __forceinline__ float selu(float v) {
    const float S  = 1.0507009873554805f;
    const float SA = 1.0507009873554805f * 1.6732632423543772f;
    return (v > 0.f) ? S * v : SA * (__expf(v) - 1.f);
}

// ---------------------------------------------------------------------------
// Kernel A: fp16x2 split GEMM (X@W1 per emotion) via mma.sync + fused layer2
// grid (64, 10), 256 threads, 2 CTAs/SM. (R9 structure, 2-MMA arithmetic.)
// ---------------------------------------------------------------------------
__global__ void __launch_bounds__(256, 2) mlp_tc_kernel(
    const float* __restrict__ X,    // (B,F)
    const float* __restrict__ bw,   // (E,NB)
    const float* __restrict__ W1,   // (E,F,H)
    const float* __restrict__ b1,   // (E,H)
    const float* __restrict__ W2,   // (E,H,NB)
    const float* __restrict__ b2)   // (E,NB)
{
    extern __shared__ char smem[];
    const uint32_t sb = smem_u32(smem);
    const int tid  = threadIdx.x;
    const int w    = tid >> 5;
    const int lane = tid & 31;
    const int b0   = blockIdx.x * ROWS;
    const int e0   = blockIdx.y * EPC;

    for (int t = tid; t < EPC * NB_; t += 256) {
        ((float*)(smem + OFF_BW))[t] = bw[e0 * NB_ + t];
        ((float*)(smem + OFF_B2))[t] = b2[e0 * NB_ + t];
    }
    for (int t = tid; t < EPC * H_; t += 256)
        ((float*)(smem + OFF_B1))[t] = b1[e0 * H_ + t];
    for (int t = tid; t < EPC * H_ * NB_; t += 256)
        ((float*)(smem + OFF_W2))[t] = W2[(size_t)e0 * H_ * NB_ + t];

    float acc[EPC][4][4];
    #pragma unroll
    for (int e = 0; e < EPC; e++)
        #pragma unroll
        for (int i = 0; i < 4; i++)
            #pragma unroll
            for (int j = 0; j < 4; j++) acc[e][i][j] = 0.f;

    // X: 128 rows x 8 qgroups = 1024 tasks / 256 thr = 4
    const int xrow = tid >> 3, xq = tid & 7;
    auto ldgX = [&](float4* xv, int c) {
        const int k0 = c * KC;
        #pragma unroll
        for (int it = 0; it < 4; it++)
            xv[it] = *reinterpret_cast<const float4*>(
                &X[(size_t)(b0 + it * 32 + xrow) * F_ + k0 + xq * 4]);
    };
    auto stsX = [&](const float4* xv, int p) {
        #pragma unroll
        for (int it = 0; it < 4; it++) {
            uint32_t h01, l01, h23, l23;
            split2h(xv[it].x, xv[it].y, h01, l01);
            split2h(xv[it].z, xv[it].w, h23, l23);
            int off = (it * 32 + xrow) * 80 + xq * 8;
            *reinterpret_cast<uint2*>(smem + XHI(p) + off) = make_uint2(h01, h23);
            *reinterpret_cast<uint2*>(smem + XLO(p) + off) = make_uint2(l01, l23);
        }
    };
    // W: 3e x 32 rows x 8 q = 768 tasks / 256 thr = 3
    auto ldgW = [&](float4* wv, int c) {
        const int k0 = c * KC;
        #pragma unroll
        for (int it = 0; it < 3; it++) {
            int g = it * 256 + tid;
            int e = g >> 8, r = g & 255;
            int kr = r >> 3, q = r & 7;
            wv[it] = *reinterpret_cast<const float4*>(
                &W1[((size_t)(e0 + e) * F_ + k0 + kr) * H_ + q * 4]);
        }
    };
    auto stsW = [&](const float4* wv, int p) {
        #pragma unroll
        for (int it = 0; it < 3; it++) {
            int g = it * 256 + tid;
            int e = g >> 8, r = g & 255;
            int kr = r >> 3, q = r & 7;
            uint32_t h01 = cvt2h(wv[it].x, wv[it].y);
            uint32_t h23 = cvt2h(wv[it].z, wv[it].w);
            *reinterpret_cast<uint2*>(smem + WH(p) + e * 2560 + kr * 80 + q * 8) =
                make_uint2(h01, h23);
        }
    };

    {
        float4 xv[4], wv[3];
        ldgX(xv, 0); ldgW(wv, 0);
        stsX(xv, 0); stsW(wv, 0);
    }
    __syncthreads();

    const int lr16 = lane & 15;
    const int lq16 = (lane >> 4) * 16;

    for (int c = 0; c < NCH; c++) {
        const int p = c & 1;

        float4 xv[4], wv[3];
        if (c + 1 < NCH) { ldgX(xv, c + 1); ldgW(wv, c + 1); }

        #pragma unroll
        for (int ks = 0; ks < 2; ks++) {
            uint32_t Ah[4], Al[4];
            uint32_t ar = sb + XHI(p) + (uint32_t)((w * 16 + lr16) * 80 + ks * 32 + lq16);
            ldmx4(Ah, ar);
            ldmx4(Al, ar + 10240);
            #pragma unroll
            for (int e = 0; e < EPC; e++) {
                uint32_t br = sb + WH(p) +
                    (uint32_t)(e * 2560 + (ks * 16 + lr16) * 80 + lq16);
                #pragma unroll
                for (int np = 0; np < 2; np++) {
                    uint32_t Bh[4];
                    ldmx4t(Bh, br + np * 32);
                    #pragma unroll
                    for (int t = 0; t < 2; t++) {
                        float* C = acc[e][np * 2 + t];
                        mma_f16(C, Ah, &Bh[t * 2]);
                        mma_f16(C, Al, &Bh[t * 2]);
                    }
                }
            }
        }

        if (c + 1 < NCH) { stsX(xv, p ^ 1); stsW(wv, p ^ 1); }
        __syncthreads();
    }

    // -------- epilogue --------
    float* Hs = (float*)(smem + OFF_X);          // [128][33]
    const float* b1s = (const float*)(smem + OFF_B1);
    const float* b2s = (const float*)(smem + OFF_B2);
    const float* bws = (const float*)(smem + OFF_BW);
    const float* W2s = (const float*)(smem + OFF_W2);

    for (int e = 0; e < EPC; e++) {
        const int r0 = w * 16 + (lane >> 2);
        #pragma unroll
        for (int nt = 0; nt < 4; nt++) {
            int col = nt * 8 + (lane & 3) * 2;
            float ba = b1s[e * H_ + col], bb = b1s[e * H_ + col + 1];
            const float* C = acc[e][nt];
            Hs[r0 * 33 + col]           = selu(C[0] + ba);
            Hs[r0 * 33 + col + 1]       = selu(C[1] + bb);
            Hs[(r0 + 8) * 33 + col]     = selu(C[2] + ba);
            Hs[(r0 + 8) * 33 + col + 1] = selu(C[3] + bb);
        }
        __syncthreads();

        if (tid < ROWS) {
            float h[H_];
            #pragma unroll
            for (int hh = 0; hh < H_; hh++) h[hh] = Hs[tid * 33 + hh];

            float ew[NB_]; float s = 0.f;
            #pragma unroll
            for (int n = 0; n < NB_; n++) { ew[n] = __expf(bws[e * NB_ + n]); s += ew[n]; }
            const float inv_s = 1.f / fmaxf(s, EPS_);

            float upd[NB_]; float sa = 0.f;
            #pragma unroll
            for (int n = 0; n < NB_; n++) {
                float a2 = b2s[e * NB_ + n];
                #pragma unroll
                for (int hh = 0; hh < H_; hh++)
                    a2 = fmaf(h[hh], W2s[e * H_ * NB_ + hh * NB_ + n], a2);
                float u = fmaf(ew[n], inv_s, a2);
                upd[n] = u;
                sa += fabsf(u);
            }
            const float inv = 1.f / fmaxf(sa, EPS_);

            float4* dst = reinterpret_cast<float4*>(
                &g_w[((size_t)(e0 + e) * B_ + b0 + tid) * NB_]);
            dst[0] = make_float4(upd[0] * inv, upd[1] * inv, upd[2]  * inv, upd[3]  * inv);
            dst[1] = make_float4(upd[4] * inv, upd[5] * inv, upd[6]  * inv, upd[7]  * inv);
            dst[2] = make_float4(upd[8] * inv, upd[9] * inv, upd[10] * inv, upd[11] * inv);
        }
        __syncthreads();
    }
}

// ---------------------------------------------------------------------------
// Kernel B: mixed = w @ D, softmax over L (|mixed| < 1 -> no max pass).
// ---------------------------------------------------------------------------
__global__ __launch_bounds__(128, 7) void mix_softmax_kernel(
    const float* __restrict__ D, float* __restrict__ out)
{
    const int warp = threadIdx.x >> 5;
    const int lane = threadIdx.x & 31;
    const size_t b = (size_t)blockIdx.x * 4 + warp;

    float4 Dreg[NB_];
    #pragma unroll
    for (int n = 0; n < NB_; n++)
        Dreg[n] = *reinterpret_cast<const float4*>(
            &D[(b * NB_ + n) * L_ + lane * 4]);

    const float* wp = &g_w[b * NB_];
    float wv_next = (lane < NB_) ? wp[lane] : 0.f;

    for (int e = 0; e < E_; e++) {
        float wvv = wv_next;
        if (e + 1 < E_)
            wv_next = (lane < NB_) ? wp[(size_t)(e + 1) * B_ * NB_ + lane] : 0.f;

        float4 v = make_float4(0.f, 0.f, 0.f, 0.f);
        #pragma unroll
        for (int n = 0; n < NB_; n++) {
            float wn = __shfl_sync(0xffffffffu, wvv, n);
            v.x = fmaf(wn, Dreg[n].x, v.x);
            v.y = fmaf(wn, Dreg[n].y, v.y);
            v.z = fmaf(wn, Dreg[n].z, v.z);
            v.w = fmaf(wn, Dreg[n].w, v.w);
        }
        float e0 = __expf(v.x), e1 = __expf(v.y);
        float e2 = __expf(v.z), e3 = __expf(v.w);
        float sm = (e0 + e1) + (e2 + e3);
        #pragma unroll
        for (int off = 16; off > 0; off >>= 1)
            sm += __shfl_xor_sync(0xffffffffu, sm, off);
        const float inv = 1.f / sm;
        *reinterpret_cast<float4*>(&out[((size_t)e * B_ + b) * L_ + lane * 4]) =
            make_float4(e0 * inv, e1 * inv, e2 * inv, e3 * inv);
    }
}

// ---------------------------------------------------------------------------
extern "C" void kernel_launch(void* const* d_in, const int* in_sizes, int n_in,
                              void* d_out, int out_size)
{
    const float* D  = (const float*)d_in[0];
    const float* X  = (const float*)d_in[1];
    const float* bw = (const float*)d_in[2];
    const float* W1 = (const float*)d_in[3];
    const float* b1 = (const float*)d_in[4];
    const float* W2 = (const float*)d_in[5];
    const float* b2 = (const float*)d_in[6];
    float* out = (float*)d_out;

    cudaFuncSetAttribute(mlp_tc_kernel,
                         cudaFuncAttributeMaxDynamicSharedMemorySize, SMEM_BYTES);
    dim3 gA(B_ / ROWS, NEG);
    mlp_tc_kernel<<<gA, 256, SMEM_BYTES>>>(X, bw, W1, b1, W2, b2);
    mix_softmax_kernel<<<B_ / 4, 128>>>(D, out);
}

// round 16
// speedup vs baseline: 1.6113x; 1.5163x over previous
#include <cuda_runtime.h>
#include <cuda_fp16.h>
#include <cstdint>
#include <math.h>

#define E_   30
#define NB_  12
#define F_   1024
#define H_   32
#define B_   8192
#define L_   128
#define EPS_ 1e-12f

#define EPC  3            // emotions per CTA
#define NEG  10           // emotion groups
#define ROWS 128          // B rows per CTA
#define KC   32           // k per chunk
#define NCH  (F_ / KC)    // 32 chunks

__device__ float g_w[E_ * B_ * NB_];
__device__ __half g_Xh[B_ * F_], g_Xl[B_ * F_];   // fp16 split of X
__device__ __half g_Wh[E_ * F_ * H_];             // fp16 W1

// ---------------- smem layout (bytes) — identical to R15 ----------------
#define OFF_BW   0
#define OFF_B2   256
#define OFF_B1   512
#define OFF_W2   1024                    // 3*384 f = 4608B
#define OFF_X    5888
#define BUFSZ    28160                   // XHI 10240 + XLO 10240 + WH 7680
#define XHI(p)   (OFF_X + (p) * BUFSZ)
#define XLO(p)   (XHI(p) + 10240)
#define WH(p)    (XHI(p) + 20480)
#define SMEM_BYTES (OFF_X + 2 * BUFSZ)   // 62208 -> 2 CTAs/SM

__device__ __forceinline__ uint32_t smem_u32(const void* p) {
    uint32_t a;
    asm("{ .reg .u64 t; cvta.to.shared.u64 t, %1; cvt.u32.u64 %0, t; }"
        : "=r"(a) : "l"(p));
    return a;
}
#define CP16(dst, src) \
    asm volatile("cp.async.cg.shared.global [%0], [%1], 16;" \
        :: "r"((uint32_t)(dst)), "l"(src) : "memory")
#define CPCOMMIT() asm volatile("cp.async.commit_group;" ::: "memory")
#define CPWAIT0()  asm volatile("cp.async.wait_group 0;" ::: "memory")

__device__ __forceinline__ void ldmx4(uint32_t* r, uint32_t a) {
    asm volatile("ldmatrix.sync.aligned.m8n8.x4.shared.b16 {%0,%1,%2,%3}, [%4];"
        : "=r"(r[0]), "=r"(r[1]), "=r"(r[2]), "=r"(r[3]) : "r"(a));
}
__device__ __forceinline__ void ldmx4t(uint32_t* r, uint32_t a) {
    asm volatile("ldmatrix.sync.aligned.m8n8.x4.trans.shared.b16 {%0,%1,%2,%3}, [%4];"
        : "=r"(r[0]), "=r"(r[1]), "=r"(r[2]), "=r"(r[3]) : "r"(a));
}
__device__ __forceinline__ void mma_f16(float* c, const uint32_t* a, const uint32_t* b) {
    asm volatile(
        "mma.sync.aligned.m16n8k16.row.col.f32.f16.f16.f32 "
        "{%0,%1,%2,%3}, {%4,%5,%6,%7}, {%8,%9}, {%0,%1,%2,%3};"
        : "+f"(c[0]), "+f"(c[1]), "+f"(c[2]), "+f"(c[3])
        : "r"(a[0]), "r"(a[1]), "r"(a[2]), "r"(a[3]), "r"(b[0]), "r"(b[1]));
}
__device__ __forceinline__ float selu(float v) {
    const float S  = 1.0507009873554805f;
    const float SA = 1.0507009873554805f * 1.6732632423543772f;
    return (v > 0.f) ? S * v : SA * (__expf(v) - 1.f);
}

// ---------------------------------------------------------------------------
// Prep: split X -> hi/lo fp16, round W1 -> fp16. Flat over 16B quads.
// ---------------------------------------------------------------------------
#define NX4 (B_ * F_ / 4)                 // 2097152
#define NW4 (E_ * F_ * H_ / 4)            // 245760
__global__ __launch_bounds__(256) void split_kernel(
    const float* __restrict__ X, const float* __restrict__ W1)
{
    int i = blockIdx.x * 256 + threadIdx.x;
    if (i < NX4) {
        float4 v = reinterpret_cast<const float4*>(X)[i];
        __half h0 = __float2half(v.x), h1 = __float2half(v.y);
        __half h2 = __float2half(v.z), h3 = __float2half(v.w);
        __half l0 = __float2half(v.x - __half2float(h0));
        __half l1 = __float2half(v.y - __half2float(h1));
        __half l2 = __float2half(v.z - __half2float(h2));
        __half l3 = __float2half(v.w - __half2float(h3));
        uint32_t ha = (uint32_t)__half_as_ushort(h0) | ((uint32_t)__half_as_ushort(h1) << 16);
        uint32_t hb = (uint32_t)__half_as_ushort(h2) | ((uint32_t)__half_as_ushort(h3) << 16);
        uint32_t la = (uint32_t)__half_as_ushort(l0) | ((uint32_t)__half_as_ushort(l1) << 16);
        uint32_t lb = (uint32_t)__half_as_ushort(l2) | ((uint32_t)__half_as_ushort(l3) << 16);
        reinterpret_cast<uint2*>(g_Xh)[i] = make_uint2(ha, hb);
        reinterpret_cast<uint2*>(g_Xl)[i] = make_uint2(la, lb);
    } else if (i < NX4 + NW4) {
        int j = i - NX4;
        float4 v = reinterpret_cast<const float4*>(W1)[j];
        uint32_t ha = (uint32_t)__half_as_ushort(__float2half(v.x)) |
                      ((uint32_t)__half_as_ushort(__float2half(v.y)) << 16);
        uint32_t hb = (uint32_t)__half_as_ushort(__float2half(v.z)) |
                      ((uint32_t)__half_as_ushort(__float2half(v.w)) << 16);
        reinterpret_cast<uint2*>(g_Wh)[j] = make_uint2(ha, hb);
    }
}

// ---------------------------------------------------------------------------
// Kernel A: fp16x2 split GEMM, staging via cp.async only (no LDG/cvt/STS).
// grid (64, 10), 256 threads, 2 CTAs/SM.
// ---------------------------------------------------------------------------
__global__ void __launch_bounds__(256, 2) mlp_tc_kernel(
    const float* __restrict__ bw,   // (E,NB)
    const float* __restrict__ b1,   // (E,H)
    const float* __restrict__ W2,   // (E,H,NB)
    const float* __restrict__ b2)   // (E,NB)
{
    extern __shared__ char smem[];
    const uint32_t sb = smem_u32(smem);
    const int tid  = threadIdx.x;
    const int w    = tid >> 5;
    const int lane = tid & 31;
    const int b0   = blockIdx.x * ROWS;
    const int e0   = blockIdx.y * EPC;

    for (int t = tid; t < EPC * NB_; t += 256) {
        ((float*)(smem + OFF_BW))[t] = bw[e0 * NB_ + t];
        ((float*)(smem + OFF_B2))[t] = b2[e0 * NB_ + t];
    }
    for (int t = tid; t < EPC * H_; t += 256)
        ((float*)(smem + OFF_B1))[t] = b1[e0 * H_ + t];
    for (int t = tid; t < EPC * H_ * NB_; t += 256)
        ((float*)(smem + OFF_W2))[t] = W2[(size_t)e0 * H_ * NB_ + t];

    float acc[EPC][4][4];
    #pragma unroll
    for (int e = 0; e < EPC; e++)
        #pragma unroll
        for (int i = 0; i < 4; i++)
            #pragma unroll
            for (int j = 0; j < 4; j++) acc[e][i][j] = 0.f;

    // pure cp.async staging: X 512 quad-tasks (hi+lo each), W 384 quad-tasks
    auto stage = [&](int c, int p) {
        const int k0 = c * KC;
        #pragma unroll
        for (int it = 0; it < 2; it++) {
            int t = it * 256 + tid;            // 0..511
            int row = t >> 2, q = t & 3;
            size_t so = (size_t)(b0 + row) * F_ + k0 + q * 8;
            uint32_t d = sb + XHI(p) + row * 80 + q * 16;
            CP16(d, g_Xh + so);
            CP16(d + 10240, g_Xl + so);
        }
        #pragma unroll
        for (int it = 0; it < 2; it++) {
            int t = it * 256 + tid;
            if (t < 384) {
                int e = t >> 7, r = t & 127;
                int kr = r >> 2, q = r & 3;
                size_t so = ((size_t)(e0 + e) * F_ + k0 + kr) * H_ + q * 8;
                CP16(sb + WH(p) + e * 2560 + kr * 80 + q * 16, g_Wh + so);
            }
        }
    };

    stage(0, 0);
    CPCOMMIT();
    CPWAIT0();
    __syncthreads();

    const int lr16 = lane & 15;
    const int lq16 = (lane >> 4) * 16;

    for (int c = 0; c < NCH; c++) {
        const int p = c & 1;
        if (c + 1 < NCH) { stage(c + 1, p ^ 1); CPCOMMIT(); }

        #pragma unroll
        for (int ks = 0; ks < 2; ks++) {
            uint32_t Ah[4], Al[4];
            uint32_t ar = sb + XHI(p) + (uint32_t)((w * 16 + lr16) * 80 + ks * 32 + lq16);
            ldmx4(Ah, ar);
            ldmx4(Al, ar + 10240);
            #pragma unroll
            for (int e = 0; e < EPC; e++) {
                uint32_t br = sb + WH(p) +
                    (uint32_t)(e * 2560 + (ks * 16 + lr16) * 80 + lq16);
                #pragma unroll
                for (int np = 0; np < 2; np++) {
                    uint32_t Bh[4];
                    ldmx4t(Bh, br + np * 32);
                    #pragma unroll
                    for (int t = 0; t < 2; t++) {
                        float* C = acc[e][np * 2 + t];
                        mma_f16(C, Ah, &Bh[t * 2]);
                        mma_f16(C, Al, &Bh[t * 2]);
                    }
                }
            }
        }

        CPWAIT0();
        __syncthreads();
    }

    // -------- epilogue (identical to R15) --------
    float* Hs = (float*)(smem + OFF_X);          // [128][33]
    const float* b1s = (const float*)(smem + OFF_B1);
    const float* b2s = (const float*)(smem + OFF_B2);
    const float* bws = (const float*)(smem + OFF_BW);
    const float* W2s = (const float*)(smem + OFF_W2);

    for (int e = 0; e < EPC; e++) {
        const int r0 = w * 16 + (lane >> 2);
        #pragma unroll
        for (int nt = 0; nt < 4; nt++) {
            int col = nt * 8 + (lane & 3) * 2;
            float ba = b1s[e * H_ + col], bb = b1s[e * H_ + col + 1];
            const float* C = acc[e][nt];
            Hs[r0 * 33 + col]           = selu(C[0] + ba);
            Hs[r0 * 33 + col + 1]       = selu(C[1] + bb);
            Hs[(r0 + 8) * 33 + col]     = selu(C[2] + ba);
            Hs[(r0 + 8) * 33 + col + 1] = selu(C[3] + bb);
        }
        __syncthreads();

        if (tid < ROWS) {
            float h[H_];
            #pragma unroll
            for (int hh = 0; hh < H_; hh++) h[hh] = Hs[tid * 33 + hh];

            float ew[NB_]; float s = 0.f;
            #pragma unroll
            for (int n = 0; n < NB_; n++) { ew[n] = __expf(bws[e * NB_ + n]); s += ew[n]; }
            const float inv_s = 1.f / fmaxf(s, EPS_);

            float upd[NB_]; float sa = 0.f;
            #pragma unroll
            for (int n = 0; n < NB_; n++) {
                float a2 = b2s[e * NB_ + n];
                #pragma unroll
                for (int hh = 0; hh < H_; hh++)
                    a2 = fmaf(h[hh], W2s[e * H_ * NB_ + hh * NB_ + n], a2);
                float u = fmaf(ew[n], inv_s, a2);
                upd[n] = u;
                sa += fabsf(u);
            }
            const float inv = 1.f / fmaxf(sa, EPS_);

            float4* dst = reinterpret_cast<float4*>(
                &g_w[((size_t)(e0 + e) * B_ + b0 + tid) * NB_]);
            dst[0] = make_float4(upd[0] * inv, upd[1] * inv, upd[2]  * inv, upd[3]  * inv);
            dst[1] = make_float4(upd[4] * inv, upd[5] * inv, upd[6]  * inv, upd[7]  * inv);
            dst[2] = make_float4(upd[8] * inv, upd[9] * inv, upd[10] * inv, upd[11] * inv);
        }
        __syncthreads();
    }
}

// ---------------------------------------------------------------------------
// Kernel B: mixed = w @ D, softmax over L (|mixed| < 1 -> no max pass).
// ---------------------------------------------------------------------------
__global__ __launch_bounds__(128, 7) void mix_softmax_kernel(
    const float* __restrict__ D, float* __restrict__ out)
{
    const int warp = threadIdx.x >> 5;
    const int lane = threadIdx.x & 31;
    const size_t b = (size_t)blockIdx.x * 4 + warp;

    float4 Dreg[NB_];
    #pragma unroll
    for (int n = 0; n < NB_; n++)
        Dreg[n] = *reinterpret_cast<const float4*>(
            &D[(b * NB_ + n) * L_ + lane * 4]);

    const float* wp = &g_w[b * NB_];
    float wv_next = (lane < NB_) ? wp[lane] : 0.f;

    for (int e = 0; e < E_; e++) {
        float wvv = wv_next;
        if (e + 1 < E_)
            wv_next = (lane < NB_) ? wp[(size_t)(e + 1) * B_ * NB_ + lane] : 0.f;

        float4 v = make_float4(0.f, 0.f, 0.f, 0.f);
        #pragma unroll
        for (int n = 0; n < NB_; n++) {
            float wn = __shfl_sync(0xffffffffu, wvv, n);
            v.x = fmaf(wn, Dreg[n].x, v.x);
            v.y = fmaf(wn, Dreg[n].y, v.y);
            v.z = fmaf(wn, Dreg[n].z, v.z);
            v.w = fmaf(wn, Dreg[n].w, v.w);
        }
        float e0 = __expf(v.x), e1 = __expf(v.y);
        float e2 = __expf(v.z), e3 = __expf(v.w);
        float sm = (e0 + e1) + (e2 + e3);
        #pragma unroll
        for (int off = 16; off > 0; off >>= 1)
            sm += __shfl_xor_sync(0xffffffffu, sm, off);
        const float inv = 1.f / sm;
        *reinterpret_cast<float4*>(&out[((size_t)e * B_ + b) * L_ + lane * 4]) =
            make_float4(e0 * inv, e1 * inv, e2 * inv, e3 * inv);
    }
}

// ---------------------------------------------------------------------------
extern "C" void kernel_launch(void* const* d_in, const int* in_sizes, int n_in,
                              void* d_out, int out_size)
{
    const float* D  = (const float*)d_in[0];
    const float* X  = (const float*)d_in[1];
    const float* bw = (const float*)d_in[2];
    const float* W1 = (const float*)d_in[3];
    const float* b1 = (const float*)d_in[4];
    const float* W2 = (const float*)d_in[5];
    const float* b2 = (const float*)d_in[6];
    float* out = (float*)d_out;

    cudaFuncSetAttribute(mlp_tc_kernel,
                         cudaFuncAttributeMaxDynamicSharedMemorySize, SMEM_BYTES);

    split_kernel<<<(NX4 + NW4 + 255) / 256, 256>>>(X, W1);
    dim3 gA(B_ / ROWS, NEG);
    mlp_tc_kernel<<<gA, 256, SMEM_BYTES>>>(bw, b1, W2, b2);
    mix_softmax_kernel<<<B_ / 4, 128>>>(D, out);
}

// round 17
// speedup vs baseline: 2.1848x; 1.3559x over previous
#include <cuda_runtime.h>
#include <cuda_fp16.h>
#include <cstdint>
#include <math.h>

#define E_   30
#define NB_  12
#define F_   1024
#define H_   32
#define B_   8192
#define L_   128
#define EPS_ 1e-12f

#define EPC  3            // emotions per CTA
#define NEG  10           // emotion groups
#define ROWS 128          // B rows per CTA
#define KC   32           // k per chunk
#define NCH  (F_ / KC)    // 32 chunks

__device__ float g_w[E_ * B_ * NB_];
__device__ __half g_Xh[B_ * F_], g_Xl[B_ * F_];   // fp16 split of X
__device__ __half g_Wh[E_ * F_ * H_];             // fp16 W1

// ---------------- smem layout (bytes) ----------------
#define OFF_BW   0
#define OFF_B2   256
#define OFF_B1   512
#define OFF_W2   1024                    // 3*384 f = 4608B
#define OFF_X    5888
#define BUFSZ    28160                   // XHI 10240 + XLO 10240 + WH 7680
#define XHI(p)   (OFF_X + (p) * BUFSZ)
#define XLO(p)   (XHI(p) + 10240)
#define WH(p)    (XHI(p) + 20480)
#define SMEM_BYTES (OFF_X + 2 * BUFSZ)   // 62208 -> 2 CTAs/SM

__device__ __forceinline__ uint32_t smem_u32(const void* p) {
    uint32_t a;
    asm("{ .reg .u64 t; cvta.to.shared.u64 t, %1; cvt.u32.u64 %0, t; }"
        : "=r"(a) : "l"(p));
    return a;
}
#define CP16(dst, src) \
    asm volatile("cp.async.cg.shared.global [%0], [%1], 16;" \
        :: "r"((uint32_t)(dst)), "l"(src) : "memory")
#define CPCOMMIT() asm volatile("cp.async.commit_group;" ::: "memory")
#define CPWAIT0()  asm volatile("cp.async.wait_group 0;" ::: "memory")

__device__ __forceinline__ void ldmx4(uint32_t* r, uint32_t a) {
    asm volatile("ldmatrix.sync.aligned.m8n8.x4.shared.b16 {%0,%1,%2,%3}, [%4];"
        : "=r"(r[0]), "=r"(r[1]), "=r"(r[2]), "=r"(r[3]) : "r"(a));
}
__device__ __forceinline__ void ldmx4t(uint32_t* r, uint32_t a) {
    asm volatile("ldmatrix.sync.aligned.m8n8.x4.trans.shared.b16 {%0,%1,%2,%3}, [%4];"
        : "=r"(r[0]), "=r"(r[1]), "=r"(r[2]), "=r"(r[3]) : "r"(a));
}
// f32-accumulator HMMA (hi term)
__device__ __forceinline__ void mma_f16(float* c, const uint32_t* a, const uint32_t* b) {
    asm volatile(
        "mma.sync.aligned.m16n8k16.row.col.f32.f16.f16.f32 "
        "{%0,%1,%2,%3}, {%4,%5,%6,%7}, {%8,%9}, {%0,%1,%2,%3};"
        : "+f"(c[0]), "+f"(c[1]), "+f"(c[2]), "+f"(c[3])
        : "r"(a[0]), "r"(a[1]), "r"(a[2]), "r"(a[3]), "r"(b[0]), "r"(b[1]));
}
// f16-accumulator HMMA (lo term; 2x rate on mma.sync fallback paths)
__device__ __forceinline__ void mma_f16a(uint32_t* c, const uint32_t* a, const uint32_t* b) {
    asm volatile(
        "mma.sync.aligned.m16n8k16.row.col.f16.f16.f16.f16 "
        "{%0,%1}, {%2,%3,%4,%5}, {%6,%7}, {%0,%1};"
        : "+r"(c[0]), "+r"(c[1])
        : "r"(a[0]), "r"(a[1]), "r"(a[2]), "r"(a[3]), "r"(b[0]), "r"(b[1]));
}
__device__ __forceinline__ float ex2f(float x) {
    float r; asm("ex2.approx.f32 %0, %1;" : "=f"(r) : "f"(x)); return r;
}
__device__ __forceinline__ float rcpf(float x) {
    float r; asm("rcp.approx.f32 %0, %1;" : "=f"(r) : "f"(x)); return r;
}
__device__ __forceinline__ float selu(float v) {
    const float S  = 1.0507009873554805f;
    const float SA = 1.0507009873554805f * 1.6732632423543772f;
    return (v > 0.f) ? S * v : SA * (__expf(v) - 1.f);
}

// ---------------------------------------------------------------------------
// Prep: split X -> hi/lo fp16, round W1 -> fp16. Flat over 16B quads.
// ---------------------------------------------------------------------------
#define NX4 (B_ * F_ / 4)                 // 2097152
#define NW4 (E_ * F_ * H_ / 4)            // 245760
__global__ __launch_bounds__(256) void split_kernel(
    const float* __restrict__ X, const float* __restrict__ W1)
{
    int i = blockIdx.x * 256 + threadIdx.x;
    if (i < NX4) {
        float4 v = reinterpret_cast<const float4*>(X)[i];
        __half h0 = __float2half(v.x), h1 = __float2half(v.y);
        __half h2 = __float2half(v.z), h3 = __float2half(v.w);
        __half l0 = __float2half(v.x - __half2float(h0));
        __half l1 = __float2half(v.y - __half2float(h1));
        __half l2 = __float2half(v.z - __half2float(h2));
        __half l3 = __float2half(v.w - __half2float(h3));
        uint32_t ha = (uint32_t)__half_as_ushort(h0) | ((uint32_t)__half_as_ushort(h1) << 16);
        uint32_t hb = (uint32_t)__half_as_ushort(h2) | ((uint32_t)__half_as_ushort(h3) << 16);
        uint32_t la = (uint32_t)__half_as_ushort(l0) | ((uint32_t)__half_as_ushort(l1) << 16);
        uint32_t lb = (uint32_t)__half_as_ushort(l2) | ((uint32_t)__half_as_ushort(l3) << 16);
        reinterpret_cast<uint2*>(g_Xh)[i] = make_uint2(ha, hb);
        reinterpret_cast<uint2*>(g_Xl)[i] = make_uint2(la, lb);
    } else if (i < NX4 + NW4) {
        int j = i - NX4;
        float4 v = reinterpret_cast<const float4*>(W1)[j];
        uint32_t ha = (uint32_t)__half_as_ushort(__float2half(v.x)) |
                      ((uint32_t)__half_as_ushort(__float2half(v.y)) << 16);
        uint32_t hb = (uint32_t)__half_as_ushort(__float2half(v.z)) |
                      ((uint32_t)__half_as_ushort(__float2half(v.w)) << 16);
        reinterpret_cast<uint2*>(g_Wh)[j] = make_uint2(ha, hb);
    }
}

// ---------------------------------------------------------------------------
// Kernel A: fp16x2 split GEMM (hi f32-acc, lo f16-acc), cp.async staging.
// grid (64, 10), 256 threads, 2 CTAs/SM.
// ---------------------------------------------------------------------------
__global__ void __launch_bounds__(256, 2) mlp_tc_kernel(
    const float* __restrict__ bw,   // (E,NB)
    const float* __restrict__ b1,   // (E,H)
    const float* __restrict__ W2,   // (E,H,NB)
    const float* __restrict__ b2)   // (E,NB)
{
    extern __shared__ char smem[];
    const uint32_t sb = smem_u32(smem);
    const int tid  = threadIdx.x;
    const int w    = tid >> 5;
    const int lane = tid & 31;
    const int b0   = blockIdx.x * ROWS;
    const int e0   = blockIdx.y * EPC;

    for (int t = tid; t < EPC * NB_; t += 256) {
        ((float*)(smem + OFF_BW))[t] = bw[e0 * NB_ + t];
        ((float*)(smem + OFF_B2))[t] = b2[e0 * NB_ + t];
    }
    for (int t = tid; t < EPC * H_; t += 256)
        ((float*)(smem + OFF_B1))[t] = b1[e0 * H_ + t];
    for (int t = tid; t < EPC * H_ * NB_; t += 256)
        ((float*)(smem + OFF_W2))[t] = W2[(size_t)e0 * H_ * NB_ + t];

    float acc[EPC][4][4];            // hi, f32 accum
    uint32_t accl[EPC][4][2];        // lo, f16 accum (packed h2)
    #pragma unroll
    for (int e = 0; e < EPC; e++)
        #pragma unroll
        for (int i = 0; i < 4; i++) {
            #pragma unroll
            for (int j = 0; j < 4; j++) acc[e][i][j] = 0.f;
            accl[e][i][0] = 0u; accl[e][i][1] = 0u;
        }

    auto stage = [&](int c, int p) {
        const int k0 = c * KC;
        #pragma unroll
        for (int it = 0; it < 2; it++) {
            int t = it * 256 + tid;            // 0..511
            int row = t >> 2, q = t & 3;
            size_t so = (size_t)(b0 + row) * F_ + k0 + q * 8;
            uint32_t d = sb + XHI(p) + row * 80 + q * 16;
            CP16(d, g_Xh + so);
            CP16(d + 10240, g_Xl + so);
        }
        #pragma unroll
        for (int it = 0; it < 2; it++) {
            int t = it * 256 + tid;
            if (t < 384) {
                int e = t >> 7, r = t & 127;
                int kr = r >> 2, q = r & 3;
                size_t so = ((size_t)(e0 + e) * F_ + k0 + kr) * H_ + q * 8;
                CP16(sb + WH(p) + e * 2560 + kr * 80 + q * 16, g_Wh + so);
            }
        }
    };

    stage(0, 0);
    CPCOMMIT();
    CPWAIT0();
    __syncthreads();

    const int lr16 = lane & 15;
    const int lq16 = (lane >> 4) * 16;

    for (int c = 0; c < NCH; c++) {
        const int p = c & 1;
        if (c + 1 < NCH) { stage(c + 1, p ^ 1); CPCOMMIT(); }

        #pragma unroll
        for (int ks = 0; ks < 2; ks++) {
            uint32_t Ah[4], Al[4];
            uint32_t ar = sb + XHI(p) + (uint32_t)((w * 16 + lr16) * 80 + ks * 32 + lq16);
            ldmx4(Ah, ar);
            ldmx4(Al, ar + 10240);
            #pragma unroll
            for (int e = 0; e < EPC; e++) {
                uint32_t br = sb + WH(p) +
                    (uint32_t)(e * 2560 + (ks * 16 + lr16) * 80 + lq16);
                #pragma unroll
                for (int np = 0; np < 2; np++) {
                    uint32_t Bh[4];
                    ldmx4t(Bh, br + np * 32);
                    #pragma unroll
                    for (int t = 0; t < 2; t++) {
                        mma_f16(acc[e][np * 2 + t], Ah, &Bh[t * 2]);
                        mma_f16a(accl[e][np * 2 + t], Al, &Bh[t * 2]);
                    }
                }
            }
        }

        CPWAIT0();
        __syncthreads();
    }

    // -------- epilogue --------
    float* Hs = (float*)(smem + OFF_X);          // [128][33]
    const float* b1s = (const float*)(smem + OFF_B1);
    const float* b2s = (const float*)(smem + OFF_B2);
    const float* bws = (const float*)(smem + OFF_BW);
    const float* W2s = (const float*)(smem + OFF_W2);

    for (int e = 0; e < EPC; e++) {
        const int r0 = w * 16 + (lane >> 2);
        #pragma unroll
        for (int nt = 0; nt < 4; nt++) {
            int col = nt * 8 + (lane & 3) * 2;
            float ba = b1s[e * H_ + col], bb = b1s[e * H_ + col + 1];
            const float* C = acc[e][nt];
            float2 lo01 = __half22float2(*reinterpret_cast<const __half2*>(&accl[e][nt][0]));
            float2 lo23 = __half22float2(*reinterpret_cast<const __half2*>(&accl[e][nt][1]));
            Hs[r0 * 33 + col]           = selu(C[0] + lo01.x + ba);
            Hs[r0 * 33 + col + 1]       = selu(C[1] + lo01.y + bb);
            Hs[(r0 + 8) * 33 + col]     = selu(C[2] + lo23.x + ba);
            Hs[(r0 + 8) * 33 + col + 1] = selu(C[3] + lo23.y + bb);
        }
        __syncthreads();

        if (tid < ROWS) {
            float h[H_];
            #pragma unroll
            for (int hh = 0; hh < H_; hh++) h[hh] = Hs[tid * 33 + hh];

            float ew[NB_]; float s = 0.f;
            #pragma unroll
            for (int n = 0; n < NB_; n++) { ew[n] = __expf(bws[e * NB_ + n]); s += ew[n]; }
            const float inv_s = 1.f / fmaxf(s, EPS_);

            float upd[NB_]; float sa = 0.f;
            #pragma unroll
            for (int n = 0; n < NB_; n++) {
                float a2 = b2s[e * NB_ + n];
                #pragma unroll
                for (int hh = 0; hh < H_; hh++)
                    a2 = fmaf(h[hh], W2s[e * H_ * NB_ + hh * NB_ + n], a2);
                float u = fmaf(ew[n], inv_s, a2);
                upd[n] = u;
                sa += fabsf(u);
            }
            const float inv = 1.f / fmaxf(sa, EPS_);

            float4* dst = reinterpret_cast<float4*>(
                &g_w[((size_t)(e0 + e) * B_ + b0 + tid) * NB_]);
            dst[0] = make_float4(upd[0] * inv, upd[1] * inv, upd[2]  * inv, upd[3]  * inv);
            dst[1] = make_float4(upd[4] * inv, upd[5] * inv, upd[6]  * inv, upd[7]  * inv);
            dst[2] = make_float4(upd[8] * inv, upd[9] * inv, upd[10] * inv, upd[11] * inv);
        }
        __syncthreads();
    }
}

// ---------------------------------------------------------------------------
// Kernel B: mixed = w @ D, softmax over L. |mixed|<1 -> no max pass.
// w pre-scaled by log2e -> raw ex2.approx; rcp.approx for 1/sum.
// ---------------------------------------------------------------------------
__global__ __launch_bounds__(128, 7) void mix_softmax_kernel(
    const float* __restrict__ D, float* __restrict__ out)
{
    const int warp = threadIdx.x >> 5;
    const int lane = threadIdx.x & 31;
    const size_t b = (size_t)blockIdx.x * 4 + warp;
    const float LOG2E = 1.4426950408889634f;

    float4 Dreg[NB_];
    #pragma unroll
    for (int n = 0; n < NB_; n++)
        Dreg[n] = *reinterpret_cast<const float4*>(
            &D[(b * NB_ + n) * L_ + lane * 4]);

    const float* wp = &g_w[b * NB_];
    float wv_next = (lane < NB_) ? wp[lane] : 0.f;

    for (int e = 0; e < E_; e++) {
        float wvv = wv_next * LOG2E;        // fold log2e into weights
        if (e + 1 < E_)
            wv_next = (lane < NB_) ? wp[(size_t)(e + 1) * B_ * NB_ + lane] : 0.f;

        float4 v = make_float4(0.f, 0.f, 0.f, 0.f);
        #pragma unroll
        for (int n = 0; n < NB_; n++) {
            float wn = __shfl_sync(0xffffffffu, wvv, n);
            v.x = fmaf(wn, Dreg[n].x, v.x);
            v.y = fmaf(wn, Dreg[n].y, v.y);
            v.z = fmaf(wn, Dreg[n].z, v.z);
            v.w = fmaf(wn, Dreg[n].w, v.w);
        }
        // v is mixed*log2e, |v| < log2e -> ex2 directly
        float e0 = ex2f(v.x), e1 = ex2f(v.y);
        float e2 = ex2f(v.z), e3 = ex2f(v.w);
        float sm = (e0 + e1) + (e2 + e3);
        #pragma unroll
        for (int off = 16; off > 0; off >>= 1)
            sm += __shfl_xor_sync(0xffffffffu, sm, off);
        const float inv = rcpf(sm);
        *reinterpret_cast<float4*>(&out[((size_t)e * B_ + b) * L_ + lane * 4]) =
            make_float4(e0 * inv, e1 * inv, e2 * inv, e3 * inv);
    }
}

// ---------------------------------------------------------------------------
extern "C" void kernel_launch(void* const* d_in, const int* in_sizes, int n_in,
                              void* d_out, int out_size)
{
    const float* D  = (const float*)d_in[0];
    const float* X  = (const float*)d_in[1];
    const float* bw = (const float*)d_in[2];
    const float* W1 = (const float*)d_in[3];
    const float* b1 = (const float*)d_in[4];
    const float* W2 = (const float*)d_in[5];
    const float* b2 = (const float*)d_in[6];
    float* out = (float*)d_out;

    cudaFuncSetAttribute(mlp_tc_kernel,
                         cudaFuncAttributeMaxDynamicSharedMemorySize, SMEM_BYTES);

    split_kernel<<<(NX4 + NW4 + 255) / 256, 256>>>(X, W1);
    dim3 gA(B_ / ROWS, NEG);
    mlp_tc_kernel<<<gA, 256, SMEM_BYTES>>>(bw, b1, W2, b2);
    mix_softmax_kernel<<<B_ / 4, 128>>>(D, out);
}